// round 7
// baseline (speedup 1.0000x reference)
#include <cuda_runtime.h>
#include <cuda_fp16.h>
#include <mma.h>
#include <math.h>
using namespace nvcuda;

// ---- problem constants ----
#define BX   2
#define CDIM 384
#define NHD  12
#define NGRP 6
#define CGRP 64
#define HCH  32
#define LDIM 1024
#define NSD  1024
#define HIDD 1536
#define EPSLN 1e-5f

// ---- scratch ----
__device__ float  g_xn [BX*LDIM*CDIM];
__device__ __half g_xnh[BX*LDIM*CDIM];
__device__ float  g_q  [BX*LDIM*CDIM];
__device__ float  g_pos[BX*NGRP*NSD*2];
__device__ __half g_xsh[BX*NSD*CDIM];
__device__ __half g_kth[BX*CDIM*NSD];
__device__ __half g_vth[BX*CDIM*NSD];
__device__ __half g_aoh[BX*LDIM*CDIM];
__device__ float  g_x2 [BX*LDIM*CDIM];
__device__ __half g_ln2h[BX*LDIM*CDIM];
__device__ __half g_h1h[BX*LDIM*HIDD];
// half weights
__device__ __half g_wqh[CDIM*CDIM];
__device__ __half g_wkh[CDIM*CDIM];
__device__ __half g_wvh[CDIM*CDIM];
__device__ __half g_woh[CDIM*CDIM];
__device__ __half g_f1h[HIDD*CDIM];
__device__ __half g_f2h[CDIM*HIDD];

// =============================== convert f32 -> f16 ===============================
__global__ void f2h_kernel(const float* __restrict__ src, __half* __restrict__ dst)
{
    int i = blockIdx.x * 256 + threadIdx.x;
    float4 v = ((const float4*)src)[i];
    ((__half2*)dst)[2*i]   = __floats2half2_rn(v.x, v.y);
    ((__half2*)dst)[2*i+1] = __floats2half2_rn(v.z, v.w);
}

// =============================== LayerNorm ===============================
template<bool WF, bool WH>
__global__ void ln_kernel(const float* __restrict__ x, const float* __restrict__ w,
                          const float* __restrict__ b, float* __restrict__ out,
                          __half* __restrict__ outh)
{
    int row = blockIdx.x;
    int t   = threadIdx.x;         // 128
    const float* xr = x + row * CDIM;
    float v0 = xr[t], v1 = xr[t + 128], v2 = xr[t + 256];
    float s  = v0 + v1 + v2;
    float sq = v0*v0 + v1*v1 + v2*v2;
    __shared__ float sh[8];
    #pragma unroll
    for (int o = 16; o; o >>= 1) {
        s  += __shfl_down_sync(0xffffffffu, s,  o);
        sq += __shfl_down_sync(0xffffffffu, sq, o);
    }
    if ((t & 31) == 0) { sh[t >> 5] = s; sh[4 + (t >> 5)] = sq; }
    __syncthreads();
    __shared__ float s_mu, s_rstd;
    if (t == 0) {
        float S = sh[0] + sh[1] + sh[2] + sh[3];
        float SQ = sh[4] + sh[5] + sh[6] + sh[7];
        float mu = S / CDIM;
        s_mu = mu;
        s_rstd = rsqrtf(SQ / CDIM - mu * mu + EPSLN);
    }
    __syncthreads();
    float mu = s_mu, rstd = s_rstd;
    float r0 = (v0 - mu) * rstd * w[t]       + b[t];
    float r1 = (v1 - mu) * rstd * w[t + 128] + b[t + 128];
    float r2 = (v2 - mu) * rstd * w[t + 256] + b[t + 256];
    if (WF) {
        float* orow = out + row * CDIM;
        orow[t] = r0; orow[t + 128] = r1; orow[t + 256] = r2;
    }
    if (WH) {
        __half* hrow = outh + row * CDIM;
        hrow[t] = __float2half(r0); hrow[t + 128] = __float2half(r1); hrow[t + 256] = __float2half(r2);
    }
}

// =============================== WMMA GEMM ===============================
// C[M,N] = A[M,K](half) @ W[N,K](half)^T + bias; fp32 accum.
// EPI: 0=none 1=gelu 2=+res; TRANSOUT -> (B,C,ns); OUTH -> half output
template<int EPI, bool TRANSOUT, bool OUTH>
__global__ void hgemm_kernel(const __half* __restrict__ A, const __half* __restrict__ W,
                             const float* __restrict__ bias, const float* __restrict__ res,
                             void* __restrict__ outv, int M, int N, int K)
{
    __shared__ __half As[64][40];
    __shared__ __half Bs[64][40];
    __shared__ float  Cs[64][64];
    int tid = threadIdx.x;               // 128
    int m0 = blockIdx.y * 64, n0 = blockIdx.x * 64;
    int warp = tid >> 5;
    int wy = warp >> 1, wx = warp & 1;

    wmma::fragment<wmma::accumulator, 16,16,16, float> acc[2][2];
    #pragma unroll
    for (int i = 0; i < 2; i++)
        #pragma unroll
        for (int j = 0; j < 2; j++)
            wmma::fill_fragment(acc[i][j], 0.0f);

    for (int k0 = 0; k0 < K; k0 += 32) {
        #pragma unroll
        for (int j = 0; j < 2; j++) {
            int idx = tid + j * 128;
            int r = idx >> 2, c = (idx & 3) * 8;
            *(uint4*)&As[r][c] = *(const uint4*)&A[(size_t)(m0 + r) * K + k0 + c];
            *(uint4*)&Bs[r][c] = *(const uint4*)&W[(size_t)(n0 + r) * K + k0 + c];
        }
        __syncthreads();
        #pragma unroll
        for (int kk = 0; kk < 32; kk += 16) {
            wmma::fragment<wmma::matrix_a, 16,16,16, __half, wmma::row_major> a0, a1;
            wmma::fragment<wmma::matrix_b, 16,16,16, __half, wmma::col_major> b0, b1;
            wmma::load_matrix_sync(a0, &As[wy * 32][kk], 40);
            wmma::load_matrix_sync(a1, &As[wy * 32 + 16][kk], 40);
            wmma::load_matrix_sync(b0, &Bs[wx * 32][kk], 40);
            wmma::load_matrix_sync(b1, &Bs[wx * 32 + 16][kk], 40);
            wmma::mma_sync(acc[0][0], a0, b0, acc[0][0]);
            wmma::mma_sync(acc[0][1], a0, b1, acc[0][1]);
            wmma::mma_sync(acc[1][0], a1, b0, acc[1][0]);
            wmma::mma_sync(acc[1][1], a1, b1, acc[1][1]);
        }
        __syncthreads();
    }
    #pragma unroll
    for (int i = 0; i < 2; i++)
        #pragma unroll
        for (int j = 0; j < 2; j++)
            wmma::store_matrix_sync(&Cs[wy * 32 + i * 16][wx * 32 + j * 16], acc[i][j], 64, wmma::mem_row_major);
    __syncthreads();

    for (int idx = tid; idx < 4096; idx += 128) {
        int mi = idx >> 6, ni = idx & 63;
        int m = m0 + mi, n = n0 + ni;
        float c = Cs[mi][ni] + bias[n];
        if (EPI == 1) c = 0.5f * c * (1.0f + erff(c * 0.70710678118654752f));
        if (EPI == 2) c += res[(size_t)m * N + n];
        if (TRANSOUT) {
            size_t oi = (size_t)(m >> 10) * N * 1024 + (size_t)n * 1024 + (m & 1023);
            if (OUTH) ((__half*)outv)[oi] = __float2half(c);
            else      ((float*)outv)[oi] = c;
        } else if (OUTH) {
            ((__half*)outv)[(size_t)m * N + n] = __float2half(c);
        } else {
            ((float*)outv)[(size_t)m * N + n] = c;
        }
    }
}

// ========================= Offset network (fused) =========================
__global__ void offset_kernel(const float* __restrict__ q, const float* __restrict__ dww,
                              const float* __restrict__ dwb, const float* __restrict__ lnw,
                              const float* __restrict__ lnb, const float* __restrict__ pww,
                              float* __restrict__ pos)
{
    int pix = blockIdx.x;
    int c = threadIdx.x;               // 64
    int bg = pix >> 10;
    int l  = pix & 1023;
    int y = l >> 5, x = l & 31;
    int b = bg / NGRP, g = bg % NGRP;
    int ch = g * CGRP + c;
    const float* w = dww + c * 49;
    float acc = dwb[c];
    #pragma unroll
    for (int dy = -3; dy <= 3; ++dy) {
        int yy = y + dy;
        if ((unsigned)yy >= 32u) continue;
        #pragma unroll
        for (int dx = -3; dx <= 3; ++dx) {
            int xx = x + dx;
            if ((unsigned)xx >= 32u) continue;
            acc += q[(size_t)(b * LDIM + yy * 32 + xx) * CDIM + ch] * w[(dy + 3) * 7 + (dx + 3)];
        }
    }
    float s = acc, sq = acc * acc;
    #pragma unroll
    for (int o = 16; o; o >>= 1) {
        s  += __shfl_down_sync(0xffffffffu, s,  o);
        sq += __shfl_down_sync(0xffffffffu, sq, o);
    }
    __shared__ float sh[4];
    if ((c & 31) == 0) { sh[c >> 5] = s; sh[2 + (c >> 5)] = sq; }
    __syncthreads();
    float mu  = (sh[0] + sh[1]) * (1.0f / 64.0f);
    float var = (sh[2] + sh[3]) * (1.0f / 64.0f) - mu * mu;
    float r = rsqrtf(var + EPSLN);
    float o_ = (acc - mu) * r * lnw[c] + lnb[c];
    o_ = 0.5f * o_ * (1.0f + erff(o_ * 0.70710678118654752f));
    float p0 = o_ * pww[c];
    float p1 = o_ * pww[64 + c];
    #pragma unroll
    for (int o = 16; o; o >>= 1) {
        p0 += __shfl_down_sync(0xffffffffu, p0, o);
        p1 += __shfl_down_sync(0xffffffffu, p1, o);
    }
    __shared__ float ph[4];
    if ((c & 31) == 0) { ph[c >> 5] = p0; ph[2 + (c >> 5)] = p1; }
    __syncthreads();
    if (c == 0) {
        float P0 = ph[0] + ph[1];
        float P1 = ph[2] + ph[3];
        float oy = tanhf(P0) * (2.0f / 32.0f);
        float ox = tanhf(P1) * (2.0f / 32.0f);
        float py = oy + ((y + 0.5f) / 32.0f) * 2.0f - 1.0f;
        float px = ox + ((x + 0.5f) / 32.0f) * 2.0f - 1.0f;
        pos[(size_t)bg * 2048 + l * 2 + 0] = py;
        pos[(size_t)bg * 2048 + l * 2 + 1] = px;
    }
}

// ===================== Deformable bilinear sampling (half out) =====================
__global__ void sample_kernel(const float* __restrict__ xn, const float* __restrict__ pos,
                              __half* __restrict__ xs)
{
    int bn = blockIdx.x;
    int c = threadIdx.x;               // 384
    int b = bn >> 10;
    int n = bn & 1023;
    int g = c >> 6;
    float py = pos[(size_t)(b * NGRP + g) * 2048 + n * 2 + 0];
    float px = pos[(size_t)(b * NGRP + g) * 2048 + n * 2 + 1];
    float fx = (px + 1.0f) * 0.5f * 31.0f;
    float fy = (py + 1.0f) * 0.5f * 31.0f;
    float x0f = floorf(fx), y0f = floorf(fy);
    int x0 = (int)x0f, y0 = (int)y0f;
    float wx = fx - x0f, wy = fy - y0f;
    const float* base = xn + (size_t)b * LDIM * CDIM + c;
    float v = 0.0f;
    if ((unsigned)x0 < 32u && (unsigned)y0 < 32u)
        v += (1 - wx) * (1 - wy) * base[(size_t)(y0 * 32 + x0) * CDIM];
    if ((unsigned)(x0 + 1) < 32u && (unsigned)y0 < 32u)
        v += wx * (1 - wy) * base[(size_t)(y0 * 32 + x0 + 1) * CDIM];
    if ((unsigned)x0 < 32u && (unsigned)(y0 + 1) < 32u)
        v += (1 - wx) * wy * base[(size_t)((y0 + 1) * 32 + x0) * CDIM];
    if ((unsigned)(x0 + 1) < 32u && (unsigned)(y0 + 1) < 32u)
        v += wx * wy * base[(size_t)((y0 + 1) * 32 + x0 + 1) * CDIM];
    xs[(size_t)bn * CDIM + c] = __float2half(v);
}

// ========== Attention v4: WMMA QK + SIMT bias/softmax + WMMA AV ==========
#define ATH 512   // 16 warps
// smem floats-equivalent total
#define ATTN_SMEM_BYTES (131072 + 8192 + 15888 + 128 + 65536 + 2560)
__device__ __forceinline__ float rpe_bilin(const float* __restrict__ s_rpe,
                                           float qgy, float qgx, float py, float px)
{
    float fy = ((qgy - py) * 0.5f + 1.0f) * 31.0f;
    float fx = ((qgx - px) * 0.5f + 1.0f) * 31.0f;
    float x0f = floorf(fx), y0f = floorf(fy);
    int xi = (int)x0f, yi = (int)y0f;
    float wx = fx - x0f, wy = fy - y0f;
    float bias = 0.0f;
    if ((unsigned)xi < 63u && (unsigned)yi < 63u)             bias += (1 - wx) * (1 - wy) * s_rpe[yi * 63 + xi];
    if ((unsigned)(xi + 1) < 63u && (unsigned)yi < 63u)       bias += wx * (1 - wy) * s_rpe[yi * 63 + xi + 1];
    if ((unsigned)xi < 63u && (unsigned)(yi + 1) < 63u)       bias += (1 - wx) * wy * s_rpe[(yi + 1) * 63 + xi];
    if ((unsigned)(xi + 1) < 63u && (unsigned)(yi + 1) < 63u) bias += wx * wy * s_rpe[(yi + 1) * 63 + xi + 1];
    return bias;
}

__global__ void attn4_kernel(const float* __restrict__ q, const __half* __restrict__ kt,
                             const __half* __restrict__ vt, const float* __restrict__ pos,
                             const float* __restrict__ rpe, __half* __restrict__ ao)
{
    extern __shared__ float sm[];
    float*  s_logit = sm;                          // 32768 f (also AV reduction scratch)
    float*  s_pos   = sm + 32768;                  // 2048 f
    float*  s_rpe   = s_pos + 2048;                // 3972 f
    float*  s_rinv  = s_rpe + 3972;                // 32 f
    __half* s_p     = (__half*)(s_rinv + 32);      // 32768 h
    __half* s_q     = s_p + 32768;                 // 32 x 40 h

    int m0 = blockIdx.x * 32;
    int hh = blockIdx.y;
    int b  = blockIdx.z;
    int g  = hh >> 1;
    int t  = threadIdx.x;
    int w  = t >> 5, lane = t & 31;

    const float* posb = pos + (size_t)(b * NGRP + g) * 2048;
    for (int i = t; i < 3969; i += ATH) s_rpe[i] = rpe[hh * 3969 + i];
    for (int i = t; i < 2048; i += ATH) s_pos[i] = posb[i];
    for (int i = t; i < 1024; i += ATH) {
        int m = i >> 5, d = i & 31;
        s_q[m * 40 + d] = __float2half(q[(size_t)(b * LDIM + m0 + m) * CDIM + hh * HCH + d]);
    }
    __syncthreads();

    const __half* ktb = kt + ((size_t)b * CDIM + hh * HCH) * (size_t)NSD;
    const __half* vtb = vt + ((size_t)b * CDIM + hh * HCH) * (size_t)NSD;

    // ---- QK: warp w computes rows 0..31 x cols [w*64, w*64+64) ----
    {
        wmma::fragment<wmma::matrix_a, 16,16,16, __half, wmma::row_major> af[2][2];
        #pragma unroll
        for (int mi = 0; mi < 2; mi++)
            #pragma unroll
            for (int ki = 0; ki < 2; ki++)
                wmma::load_matrix_sync(af[mi][ki], &s_q[mi * 16 * 40 + ki * 16], 40);

        #pragma unroll
        for (int nf = 0; nf < 4; nf++) {
            int n = w * 64 + nf * 16;
            wmma::fragment<wmma::matrix_b, 16,16,16, __half, wmma::row_major> bf[2];
            wmma::load_matrix_sync(bf[0], ktb + n, NSD);
            wmma::load_matrix_sync(bf[1], ktb + (size_t)16 * NSD + n, NSD);
            wmma::fragment<wmma::accumulator, 16,16,16, float> acc[2];
            wmma::fill_fragment(acc[0], 0.0f);
            wmma::fill_fragment(acc[1], 0.0f);
            #pragma unroll
            for (int ki = 0; ki < 2; ki++) {
                wmma::mma_sync(acc[0], af[0][ki], bf[ki], acc[0]);
                wmma::mma_sync(acc[1], af[1][ki], bf[ki], acc[1]);
            }
            wmma::store_matrix_sync(&s_logit[0 * 16384 + n], acc[0], 1024, wmma::mem_row_major);
            wmma::store_matrix_sync(&s_logit[1 * 16384 + n], acc[1], 1024, wmma::mem_row_major);
        }
    }
    __syncthreads();

    // ---- bias + max (warp owns rows q0, q1) ----
    int q0 = 2 * w, q1 = q0 + 1;
    int mg0 = m0 + q0, mg1 = m0 + q1;
    float qgy0 = ((float)(mg0 >> 5) + 0.5f) * (1.0f / 16.0f) - 1.0f;
    float qgx0 = ((float)(mg0 & 31) + 0.5f) * (1.0f / 16.0f) - 1.0f;
    float qgy1 = ((float)(mg1 >> 5) + 0.5f) * (1.0f / 16.0f) - 1.0f;
    float qgx1 = ((float)(mg1 & 31) + 0.5f) * (1.0f / 16.0f) - 1.0f;
    const float scale = 0.17677669529663687f;
    float* L0 = s_logit + q0 * 1024;
    float* L1 = s_logit + q1 * 1024;
    float mrun0 = -1e30f, mrun1 = -1e30f;

    #pragma unroll
    for (int k = 0; k < 8; k++) {
        int n4 = lane * 4 + k * 128;
        float4 pA = *(const float4*)&s_pos[2 * n4];       // y0 x0 y1 x1
        float4 pB = *(const float4*)&s_pos[2 * n4 + 4];   // y2 x2 y3 x3
        float4 a = *(float4*)&L0[n4];
        a.x = a.x * scale + rpe_bilin(s_rpe, qgy0, qgx0, pA.x, pA.y);
        a.y = a.y * scale + rpe_bilin(s_rpe, qgy0, qgx0, pA.z, pA.w);
        a.z = a.z * scale + rpe_bilin(s_rpe, qgy0, qgx0, pB.x, pB.y);
        a.w = a.w * scale + rpe_bilin(s_rpe, qgy0, qgx0, pB.z, pB.w);
        *(float4*)&L0[n4] = a;
        mrun0 = fmaxf(mrun0, fmaxf(fmaxf(a.x, a.y), fmaxf(a.z, a.w)));
        float4 c = *(float4*)&L1[n4];
        c.x = c.x * scale + rpe_bilin(s_rpe, qgy1, qgx1, pA.x, pA.y);
        c.y = c.y * scale + rpe_bilin(s_rpe, qgy1, qgx1, pA.z, pA.w);
        c.z = c.z * scale + rpe_bilin(s_rpe, qgy1, qgx1, pB.x, pB.y);
        c.w = c.w * scale + rpe_bilin(s_rpe, qgy1, qgx1, pB.z, pB.w);
        *(float4*)&L1[n4] = c;
        mrun1 = fmaxf(mrun1, fmaxf(fmaxf(c.x, c.y), fmaxf(c.z, c.w)));
    }
    #pragma unroll
    for (int o = 16; o; o >>= 1) {
        mrun0 = fmaxf(mrun0, __shfl_xor_sync(0xffffffffu, mrun0, o));
        mrun1 = fmaxf(mrun1, __shfl_xor_sync(0xffffffffu, mrun1, o));
    }

    // ---- exp (write half P) + sum ----
    float sum0 = 0.f, sum1 = 0.f;
    #pragma unroll
    for (int k = 0; k < 8; k++) {
        int n4 = lane * 4 + k * 128;
        float4 a = *(float4*)&L0[n4];
        a.x = __expf(a.x - mrun0); a.y = __expf(a.y - mrun0);
        a.z = __expf(a.z - mrun0); a.w = __expf(a.w - mrun0);
        sum0 += a.x + a.y + a.z + a.w;
        *(__half2*)&s_p[q0 * 1024 + n4]     = __floats2half2_rn(a.x, a.y);
        *(__half2*)&s_p[q0 * 1024 + n4 + 2] = __floats2half2_rn(a.z, a.w);
        float4 c = *(float4*)&L1[n4];
        c.x = __expf(c.x - mrun1); c.y = __expf(c.y - mrun1);
        c.z = __expf(c.z - mrun1); c.w = __expf(c.w - mrun1);
        sum1 += c.x + c.y + c.z + c.w;
        *(__half2*)&s_p[q1 * 1024 + n4]     = __floats2half2_rn(c.x, c.y);
        *(__half2*)&s_p[q1 * 1024 + n4 + 2] = __floats2half2_rn(c.z, c.w);
    }
    #pragma unroll
    for (int o = 16; o; o >>= 1) {
        sum0 += __shfl_xor_sync(0xffffffffu, sum0, o);
        sum1 += __shfl_xor_sync(0xffffffffu, sum1, o);
    }
    if (lane == 0) { s_rinv[q0] = 1.0f / sum0; s_rinv[q1] = 1.0f / sum1; }
    __syncthreads();

    // ---- AV: split-k over 16 warps (each k-range 64), reduce in s_logit ----
    {
        wmma::fragment<wmma::accumulator, 16,16,16, float> oacc[2][2];
        #pragma unroll
        for (int mi = 0; mi < 2; mi++)
            #pragma unroll
            for (int di = 0; di < 2; di++)
                wmma::fill_fragment(oacc[mi][di], 0.0f);
        #pragma unroll
        for (int kf = 0; kf < 4; kf++) {
            int kk = w * 64 + kf * 16;
            wmma::fragment<wmma::matrix_a, 16,16,16, __half, wmma::row_major> pa[2];
            wmma::load_matrix_sync(pa[0], &s_p[0 * 16384 + kk], 1024);
            wmma::load_matrix_sync(pa[1], &s_p[1 * 16384 + kk], 1024);
            wmma::fragment<wmma::matrix_b, 16,16,16, __half, wmma::col_major> vb[2];
            wmma::load_matrix_sync(vb[0], vtb + kk, NSD);
            wmma::load_matrix_sync(vb[1], vtb + (size_t)16 * NSD + kk, NSD);
            #pragma unroll
            for (int mi = 0; mi < 2; mi++)
                #pragma unroll
                for (int di = 0; di < 2; di++)
                    wmma::mma_sync(oacc[mi][di], pa[mi], vb[di], oacc[mi][di]);
        }
        float* scr = s_logit + w * 1024;
        #pragma unroll
        for (int mi = 0; mi < 2; mi++)
            #pragma unroll
            for (int di = 0; di < 2; di++)
                wmma::store_matrix_sync(&scr[mi * 16 * 32 + di * 16], oacc[mi][di], 32, wmma::mem_row_major);
    }
    __syncthreads();

    #pragma unroll
    for (int idx = t; idx < 1024; idx += ATH) {
        float s = 0.f;
        #pragma unroll
        for (int ww = 0; ww < 16; ww++) s += s_logit[ww * 1024 + idx];
        int m = idx >> 5, d = idx & 31;
        ao[(size_t)(b * LDIM + m0 + m) * CDIM + hh * HCH + d] = __float2half(s * s_rinv[m]);
    }
}

// =============================== host ===============================
extern "C" void kernel_launch(void* const* d_in, const int* in_sizes, int n_in,
                              void* d_out, int out_size)
{
    const float* x     = (const float*)d_in[0];
    const float* n1w   = (const float*)d_in[1];
    const float* n1b   = (const float*)d_in[2];
    const float* wq    = (const float*)d_in[3];
    const float* bq    = (const float*)d_in[4];
    const float* wk    = (const float*)d_in[5];
    const float* bk    = (const float*)d_in[6];
    const float* wv    = (const float*)d_in[7];
    const float* bv    = (const float*)d_in[8];
    const float* wo    = (const float*)d_in[9];
    const float* bo    = (const float*)d_in[10];
    const float* dww   = (const float*)d_in[11];
    const float* dwb   = (const float*)d_in[12];
    const float* lnw   = (const float*)d_in[13];
    const float* lnb   = (const float*)d_in[14];
    const float* pww   = (const float*)d_in[15];
    const float* rpe   = (const float*)d_in[16];
    const float* n2w   = (const float*)d_in[17];
    const float* n2b   = (const float*)d_in[18];
    const float* fc1w  = (const float*)d_in[19];
    const float* fc1b  = (const float*)d_in[20];
    const float* fc2w  = (const float*)d_in[21];
    const float* fc2b  = (const float*)d_in[22];
    float* out = (float*)d_out;

    float *p_xn, *p_q, *p_pos, *p_x2;
    __half *p_xnh, *p_xsh, *p_kth, *p_vth, *p_aoh, *p_ln2h, *p_h1h;
    __half *p_wqh, *p_wkh, *p_wvh, *p_woh, *p_f1h, *p_f2h;
    cudaGetSymbolAddress((void**)&p_xn,  g_xn);
    cudaGetSymbolAddress((void**)&p_xnh, g_xnh);
    cudaGetSymbolAddress((void**)&p_q,   g_q);
    cudaGetSymbolAddress((void**)&p_pos, g_pos);
    cudaGetSymbolAddress((void**)&p_xsh, g_xsh);
    cudaGetSymbolAddress((void**)&p_kth, g_kth);
    cudaGetSymbolAddress((void**)&p_vth, g_vth);
    cudaGetSymbolAddress((void**)&p_aoh, g_aoh);
    cudaGetSymbolAddress((void**)&p_x2,  g_x2);
    cudaGetSymbolAddress((void**)&p_ln2h, g_ln2h);
    cudaGetSymbolAddress((void**)&p_h1h, g_h1h);
    cudaGetSymbolAddress((void**)&p_wqh, g_wqh);
    cudaGetSymbolAddress((void**)&p_wkh, g_wkh);
    cudaGetSymbolAddress((void**)&p_wvh, g_wvh);
    cudaGetSymbolAddress((void**)&p_woh, g_woh);
    cudaGetSymbolAddress((void**)&p_f1h, g_f1h);
    cudaGetSymbolAddress((void**)&p_f2h, g_f2h);

    const int M = BX * LDIM;   // 2048
    cudaFuncSetAttribute(attn4_kernel, cudaFuncAttributeMaxDynamicSharedMemorySize, ATTN_SMEM_BYTES);

    f2h_kernel<<<144, 256>>>(wq, p_wqh);
    f2h_kernel<<<144, 256>>>(wk, p_wkh);
    f2h_kernel<<<144, 256>>>(wv, p_wvh);
    f2h_kernel<<<144, 256>>>(wo, p_woh);
    f2h_kernel<<<576, 256>>>(fc1w, p_f1h);
    f2h_kernel<<<576, 256>>>(fc2w, p_f2h);

    ln_kernel<true, true><<<M, 128>>>(x, n1w, n1b, p_xn, p_xnh);
    hgemm_kernel<0, false, false><<<dim3(CDIM/64, M/64), 128>>>(p_xnh, p_wqh, bq, nullptr, p_q, M, CDIM, CDIM);
    offset_kernel<<<BX * NGRP * 1024, 64>>>(p_q, dww, dwb, lnw, lnb, pww, p_pos);
    sample_kernel<<<BX * NSD, CDIM>>>(p_xn, p_pos, p_xsh);
    hgemm_kernel<0, true, true><<<dim3(CDIM/64, M/64), 128>>>(p_xsh, p_wkh, bk, nullptr, p_kth, M, CDIM, CDIM);
    hgemm_kernel<0, true, true><<<dim3(CDIM/64, M/64), 128>>>(p_xsh, p_wvh, bv, nullptr, p_vth, M, CDIM, CDIM);
    attn4_kernel<<<dim3(32, NHD, BX), ATH, ATTN_SMEM_BYTES>>>(p_q, p_kth, p_vth, p_pos, rpe, p_aoh);
    hgemm_kernel<2, false, false><<<dim3(CDIM/64, M/64), 128>>>(p_aoh, p_woh, bo, x, p_x2, M, CDIM, CDIM);
    ln_kernel<false, true><<<M, 128>>>(p_x2, n2w, n2b, nullptr, p_ln2h);
    hgemm_kernel<1, false, true><<<dim3(HIDD/64, M/64), 128>>>(p_ln2h, p_f1h, fc1b, nullptr, p_h1h, M, HIDD, CDIM);
    hgemm_kernel<2, false, false><<<dim3(CDIM/64, M/64), 128>>>(p_h1h, p_f2h, fc2b, p_x2, out, M, CDIM, HIDD);
}